// round 12
// baseline (speedup 1.0000x reference)
#include <cuda_runtime.h>
#include <cuda_fp16.h>

#define NN   100000
#define EE   1600000
#define ET   (EE + NN)     // 1,700,000
#define C    128
#define DIN  6
#define HB   ((ET + 255) / 256)        // 6641 edge blocks
#define LB   ((NN * 64 + 255) / 256)   // 25000 lin blocks
#define GCN_BLOCKS (NN / 16)           // 6250 (16 nodes per 256-thr block)

typedef unsigned long long ull;

// ---------------- device scratch ----------------
__device__ __half g_xl[NN * C];    // fp16 feature table (gathered by k_gat)
__device__ float  g_xr[NN * C];    // fp32 (coalesced per-node read)
__device__ __half g_h [NN * C];    // fp16 feature table (gathered by k_gcn)
__device__ __half g_t [NN * C];    // fp16 GCN output (coalesced into gemm)
__device__ float  g_ex[ET];        // CSR-ordered exp(logit)
__device__ float  g_alpha[ET];     // CSR-ordered alpha
__device__ int    g_srca[ET];      // CSR-ordered src
__device__ float2 g_ef[ET];        // CSR-ordered edge features
__device__ int    g_pos[ET];       // original edge id -> CSR slot (coalesced)
__device__ int    g_cnt[NN];       // zero at module load; k_scan re-zeros each call
__device__ int    g_rowptr[NN + 1];
__device__ int    g_cur[NN];

// packed f32x2 helpers (Blackwell)
#define PK2(d, lo, hi)   asm("mov.b64 %0, {%1,%2};" : "=l"(d) : "f"(lo), "f"(hi))
#define UNPK2(lo, hi, s) asm("mov.b64 {%0,%1}, %2;" : "=f"(lo), "=f"(hi) : "l"(s))
#define ADD2(d, a, b)    asm("add.rn.f32x2 %0, %1, %2;" : "=l"(d) : "l"(a), "l"(b))
#define MUL2(d, a, b)    asm("mul.rn.f32x2 %0, %1, %2;" : "=l"(d) : "l"(a), "l"(b))
#define FMA2D(d, a, b, c) asm("fma.rn.f32x2 %0, %1, %2, %3;" : "=l"(d) : "l"(a), "l"(b), "l"(c))
#define FMA2(d, a, b)    asm("fma.rn.f32x2 %0, %1, %2, %0;" : "+l"(d) : "l"(a), "l"(b))
#define AND64(d, a)      asm("and.b64 %0, %1, 0x7FFFFFFF7FFFFFFF;" : "=l"(d) : "l"(a))

// load 4 fp16 channels -> float4 (8 bytes)
__device__ __forceinline__ float4 ldh4(const __half* p) {
    uint2 u = *(const uint2*)p;
    __half2 h0, h1;
    *(unsigned*)&h0 = u.x; *(unsigned*)&h1 = u.y;
    float2 f0 = __half22float2(h0), f1 = __half22float2(h1);
    return make_float4(f0.x, f0.y, f1.x, f1.y);
}

// fma 8 fp16 channels (uint4) into two float4 accumulators
__device__ __forceinline__ void fma8(float4& lo, float4& hi, uint4 u, float al) {
    float2 f0 = __half22float2(*(__half2*)&u.x);
    float2 f1 = __half22float2(*(__half2*)&u.y);
    float2 f2 = __half22float2(*(__half2*)&u.z);
    float2 f3 = __half22float2(*(__half2*)&u.w);
    lo.x += al * f0.x; lo.y += al * f0.y; lo.z += al * f1.x; lo.w += al * f1.y;
    hi.x += al * f2.x; hi.y += al * f2.y; hi.z += al * f3.x; hi.w += al * f3.y;
}

// ---------------- K1: fused setup: hist (blocks [0,HB)) + lin (blocks [HB,HB+LB)) ----------------
__global__ void k_setup(const int* __restrict__ ei, float* __restrict__ out,
                        const float* __restrict__ x,
                        const float* __restrict__ Wl, const float* __restrict__ bl,
                        const float* __restrict__ Wr, const float* __restrict__ br) {
    int b = blockIdx.x;
    if (b < HB) {
        int e = b * 256 + threadIdx.x;
        if (e >= ET) return;
        int s, d;
        if (e < EE) { s = ei[e]; d = ei[EE + e]; }
        else        { s = e - EE; d = s; }
        atomicAdd(&g_cnt[d], 1);
        out[NN * 2 + e]      = (float)s;
        out[NN * 2 + ET + e] = (float)d;
    } else {
        int idx = (b - HB) * 256 + threadIdx.x;
        if (idx >= NN * 64) return;
        int n = idx >> 6, cp = (idx & 63) * 2;
        float a0 = bl[cp], a1 = bl[cp + 1];
        float b0 = br[cp], b1 = br[cp + 1];
#pragma unroll
        for (int k = 0; k < DIN; k++) {
            float xv = x[n * DIN + k];
            a0 += xv * Wl[k * C + cp];
            a1 += xv * Wl[k * C + cp + 1];
            b0 += xv * Wr[k * C + cp];
            b1 += xv * Wr[k * C + cp + 1];
        }
        ((__half2*)g_xl)[idx] = __floats2half2_rn(a0, a1);
        *(float2*)&g_xr[n * C + cp] = make_float2(b0, b1);
    }
}

// ---------------- K2: exclusive scan (re-zeros g_cnt for next replay) ----------------
__global__ void k_scan() {
    __shared__ int ssum[1024];
    const int CH = (NN + 1023) / 1024;
    int t = threadIdx.x;
    int beg = t * CH; if (beg > NN) beg = NN;
    int end = beg + CH; if (end > NN) end = NN;
    int s = 0;
    for (int j = beg; j < end; j++) s += g_cnt[j];
    ssum[t] = s;
    __syncthreads();
    for (int off = 1; off < 1024; off <<= 1) {
        int v = (t >= off) ? ssum[t - off] : 0;
        __syncthreads();
        ssum[t] += v;
        __syncthreads();
    }
    int run = t ? ssum[t - 1] : 0;
    for (int j = beg; j < end; j++) {
        int cv = g_cnt[j];
        g_cnt[j] = 0;
        g_rowptr[j] = run;
        g_cur[j]    = run;
        run += cv;
    }
    if (t == 0) g_rowptr[NN] = ET;
}

// ---------------- K3: scatter edges into CSR slots ----------------
__global__ void k_scatter(const int* __restrict__ ei, const float* __restrict__ ew) {
    int e = blockIdx.x * blockDim.x + threadIdx.x;
    if (e >= ET) return;
    int s, d; float e0 = 0.f, e1 = 0.f;
    if (e < EE) {
        s = ei[e]; d = ei[EE + e];
        float2 v = *(const float2*)&ew[2 * e];
        e0 = v.x; e1 = v.y;
    } else { s = e - EE; d = s; }
    int pos = atomicAdd(&g_cur[d], 1);
    g_srca[pos] = s;
    g_ef[pos]   = make_float2(e0, e1);
    g_pos[e]    = pos;                // coalesced
}

// one packed pair of the GATv2 logit: m = a + xr + e0*w0 + e1*w1; r = leaky(m); pacc += r*at
__device__ __forceinline__ void gat_pair(ull a, ull xr, ull e0p, ull e1p,
                                         ull w0, ull w1, ull at,
                                         ull c04, ull c06, ull& pacc) {
    ull m0, m1, m2, am, t, r;
    ADD2(m0, a, xr);
    FMA2D(m1, e0p, w0, m0);
    FMA2D(m2, e1p, w1, m1);
    AND64(am, m2);                 // |m|
    MUL2(t, am, c04);              // 0.4|m|
    FMA2D(r, m2, c06, t);          // 0.6m + 0.4|m| == leaky_relu(m, 0.2)
    FMA2(pacc, r, at);
}

// ---------------- K4: fused GATv2 — 16-lane half-warp per edge, packed f32x2 math ----------------
__global__ void __launch_bounds__(256, 4)
k_gat(const float* __restrict__ We, const float* __restrict__ att,
      const float* __restrict__ bgat) {
    int node = (blockIdx.x * blockDim.x + threadIdx.x) >> 5;
    int lane = threadIdx.x & 31;
    if (node >= NN) return;
    int half = lane >> 4;
    int sub  = lane & 15;
    unsigned hmask = 0xFFFFu << (half * 16);
    int c = sub * 8;

    // packed per-lane constants (8 channels = 4 f32x2 pairs each)
    ull w0p[4], w1p[4], atp[4], xrp[4];
    {
        float4 A = *(const float4*)&We[c];
        float4 B = *(const float4*)&We[c + 4];
        PK2(w0p[0], A.x, A.y); PK2(w0p[1], A.z, A.w);
        PK2(w0p[2], B.x, B.y); PK2(w0p[3], B.z, B.w);
        A = *(const float4*)&We[C + c];
        B = *(const float4*)&We[C + c + 4];
        PK2(w1p[0], A.x, A.y); PK2(w1p[1], A.z, A.w);
        PK2(w1p[2], B.x, B.y); PK2(w1p[3], B.z, B.w);
        A = *(const float4*)&att[c];
        B = *(const float4*)&att[c + 4];
        PK2(atp[0], A.x, A.y); PK2(atp[1], A.z, A.w);
        PK2(atp[2], B.x, B.y); PK2(atp[3], B.z, B.w);
        A = *(const float4*)&g_xr[node * C + c];
        B = *(const float4*)&g_xr[node * C + c + 4];
        PK2(xrp[0], A.x, A.y); PK2(xrp[1], A.z, A.w);
        PK2(xrp[2], B.x, B.y); PK2(xrp[3], B.z, B.w);
    }
    ull c04, c06;
    PK2(c04, 0.4f, 0.4f);
    PK2(c06, 0.6f, 0.6f);

    int beg = g_rowptr[node], end = g_rowptr[node + 1];
    float den = 0.f;
    ull acc[4] = {0ull, 0ull, 0ull, 0ull};   // packed (0.0,0.0)

    // each half-warp walks edges beg+half, beg+half+2, ...
    for (int j = beg + half; j < end; j += 2) {
        int s = g_srca[j];                   // uniform within half
        float2 ef = g_ef[j];
        ull e0p, e1p;
        PK2(e0p, ef.x, ef.x);
        PK2(e1p, ef.y, ef.y);
        uint4 u = *(const uint4*)&g_xl[s * C + c];   // 8 fp16 channels
        float2 f0 = __half22float2(*(__half2*)&u.x);
        float2 f1 = __half22float2(*(__half2*)&u.y);
        float2 f2 = __half22float2(*(__half2*)&u.z);
        float2 f3 = __half22float2(*(__half2*)&u.w);
        ull a0, a1, a2, a3;
        PK2(a0, f0.x, f0.y); PK2(a1, f1.x, f1.y);
        PK2(a2, f2.x, f2.y); PK2(a3, f3.x, f3.y);

        ull pacc = 0ull;
        gat_pair(a0, xrp[0], e0p, e1p, w0p[0], w1p[0], atp[0], c04, c06, pacc);
        gat_pair(a1, xrp[1], e0p, e1p, w0p[1], w1p[1], atp[1], c04, c06, pacc);
        gat_pair(a2, xrp[2], e0p, e1p, w0p[2], w1p[2], atp[2], c04, c06, pacc);
        gat_pair(a3, xrp[3], e0p, e1p, w0p[3], w1p[3], atp[3], c04, c06, pacc);
        float plo, phi;
        UNPK2(plo, phi, pacc);
        float p = plo + phi;
        p += __shfl_xor_sync(hmask, p, 8);
        p += __shfl_xor_sync(hmask, p, 4);
        p += __shfl_xor_sync(hmask, p, 2);
        p += __shfl_xor_sync(hmask, p, 1);

        float v = __expf(p);
        if (sub == 0) g_ex[j] = v;
        den += v;
        ull vp; PK2(vp, v, v);
        FMA2(acc[0], vp, a0);
        FMA2(acc[1], vp, a1);
        FMA2(acc[2], vp, a2);
        FMA2(acc[3], vp, a3);
    }
    __syncwarp();

    // combine the two halves (channels are identical across halves)
    den += __shfl_xor_sync(0xffffffffu, den, 16);
    float af[8];
    UNPK2(af[0], af[1], acc[0]);
    UNPK2(af[2], af[3], acc[1]);
    UNPK2(af[4], af[5], acc[2]);
    UNPK2(af[6], af[7], acc[3]);
#pragma unroll
    for (int k = 0; k < 8; k++)
        af[k] += __shfl_xor_sync(0xffffffffu, af[k], 16);
    float inv = 1.f / den;

    // pass B: alpha write-out (full warp, coalesced)
    for (int jj = beg + lane; jj < end; jj += 32)
        g_alpha[jj] = g_ex[jj] * inv;

    if (half == 0) {
        float4 b0 = *(const float4*)&bgat[c];
        float4 b1 = *(const float4*)&bgat[c + 4];
        float h0 = fmaxf(af[0] * inv + b0.x, 0.f);
        float h1 = fmaxf(af[1] * inv + b0.y, 0.f);
        float h2 = fmaxf(af[2] * inv + b0.z, 0.f);
        float h3 = fmaxf(af[3] * inv + b0.w, 0.f);
        float h4 = fmaxf(af[4] * inv + b1.x, 0.f);
        float h5 = fmaxf(af[5] * inv + b1.y, 0.f);
        float h6 = fmaxf(af[6] * inv + b1.z, 0.f);
        float h7 = fmaxf(af[7] * inv + b1.w, 0.f);
        uint4 hu;
        *(__half2*)&hu.x = __floats2half2_rn(h0, h1);
        *(__half2*)&hu.y = __floats2half2_rn(h2, h3);
        *(__half2*)&hu.z = __floats2half2_rn(h4, h5);
        *(__half2*)&hu.w = __floats2half2_rn(h6, h7);
        *(uint4*)&g_h[node * C + c] = hu;
    }
}

// ---------------- K5: GCN aggregate (16-lane sub-warp per node, 2 nodes/warp)
//                     + aout tail blocks (alpha in original edge order) ----------------
__global__ void __launch_bounds__(256)
k_gcn(float* __restrict__ out) {
    if (blockIdx.x >= GCN_BLOCKS) {
        int e = (blockIdx.x - GCN_BLOCKS) * 256 + threadIdx.x;
        if (e < ET)
            out[(long long)NN * 2 + 2LL * ET + e] = g_alpha[g_pos[e]];
        return;
    }
    int tid  = threadIdx.x;
    int lane = tid & 31;
    int sub  = lane & 15;
    int node = (blockIdx.x * 256 + tid) >> 4;
    int c = sub * 8;
    int beg = g_rowptr[node], end = g_rowptr[node + 1];

    float4 lo0 = make_float4(0.f, 0.f, 0.f, 0.f), hi0 = lo0;
    float4 lo1 = lo0, hi1 = lo0;
    int j = beg;
    for (; j + 3 < end; j += 4) {
        int s0 = g_srca[j], s1 = g_srca[j + 1], s2 = g_srca[j + 2], s3 = g_srca[j + 3];
        float al0 = g_alpha[j],     al1 = g_alpha[j + 1];
        float al2 = g_alpha[j + 2], al3 = g_alpha[j + 3];
        uint4 u0 = *(const uint4*)&g_h[s0 * C + c];
        uint4 u1 = *(const uint4*)&g_h[s1 * C + c];
        uint4 u2 = *(const uint4*)&g_h[s2 * C + c];
        uint4 u3 = *(const uint4*)&g_h[s3 * C + c];
        fma8(lo0, hi0, u0, al0);
        fma8(lo1, hi1, u1, al1);
        fma8(lo0, hi0, u2, al2);
        fma8(lo1, hi1, u3, al3);
    }
    for (; j < end; j++) {
        int s = g_srca[j];
        float al = g_alpha[j];
        uint4 u = *(const uint4*)&g_h[s * C + c];
        fma8(lo0, hi0, u, al);
    }
    lo0.x += lo1.x; lo0.y += lo1.y; lo0.z += lo1.z; lo0.w += lo1.w;
    hi0.x += hi1.x; hi0.y += hi1.y; hi0.z += hi1.z; hi0.w += hi1.w;
    uint4 tu;
    *(__half2*)&tu.x = __floats2half2_rn(lo0.x, lo0.y);
    *(__half2*)&tu.y = __floats2half2_rn(lo0.z, lo0.w);
    *(__half2*)&tu.z = __floats2half2_rn(hi0.x, hi0.y);
    *(__half2*)&tu.w = __floats2half2_rn(hi0.z, hi0.w);
    *(uint4*)&g_t[node * C + c] = tu;
}

// ---------------- K6: out = relu(t@W2 + b_gcn) @ W3 + b3  (f32x2 GEMM) ----------------
__global__ void k_gemm(const float* __restrict__ W2, const float* __restrict__ bg,
                       const float* __restrict__ W3, const float* __restrict__ b3,
                       float* __restrict__ out) {
    __shared__ float ts[64 * C];
    int lane = threadIdx.x & 31, warp = threadIdx.x >> 5;
    int rowBase = blockIdx.x * 64;
    int c = lane * 4;

    for (int i = threadIdx.x; i < 64 * 16; i += 256) {
        int r = rowBase + (i >> 4);
        int cc = (i & 15) * 8;
        uint4 u = (r < NN) ? *(const uint4*)&g_t[r * C + cc]
                           : make_uint4(0u, 0u, 0u, 0u);
        float2 f0 = __half22float2(*(__half2*)&u.x);
        float2 f1 = __half22float2(*(__half2*)&u.y);
        float2 f2 = __half22float2(*(__half2*)&u.z);
        float2 f3 = __half22float2(*(__half2*)&u.w);
        *(float4*)&ts[(i >> 4) * C + cc]     = make_float4(f0.x, f0.y, f1.x, f1.y);
        *(float4*)&ts[(i >> 4) * C + cc + 4] = make_float4(f2.x, f2.y, f3.x, f3.y);
    }
    __syncthreads();

    ull acc2[8][2];
#pragma unroll
    for (int i = 0; i < 8; i++) { acc2[i][0] = 0ull; acc2[i][1] = 0ull; }

    for (int k4 = 0; k4 < C; k4 += 4) {
        ull wa[4], wb[4];
#pragma unroll
        for (int kk = 0; kk < 4; kk++) {
            float4 wv = __ldg((const float4*)&W2[(k4 + kk) * C + c]);
            PK2(wa[kk], wv.x, wv.y);
            PK2(wb[kk], wv.z, wv.w);
        }
#pragma unroll
        for (int i = 0; i < 8; i++) {
            float4 tv = *(const float4*)&ts[(warp * 8 + i) * C + k4];
            ull t0, t1, t2, t3;
            PK2(t0, tv.x, tv.x);
            PK2(t1, tv.y, tv.y);
            PK2(t2, tv.z, tv.z);
            PK2(t3, tv.w, tv.w);
            FMA2(acc2[i][0], t0, wa[0]); FMA2(acc2[i][1], t0, wb[0]);
            FMA2(acc2[i][0], t1, wa[1]); FMA2(acc2[i][1], t1, wb[1]);
            FMA2(acc2[i][0], t2, wa[2]); FMA2(acc2[i][1], t2, wb[2]);
            FMA2(acc2[i][0], t3, wa[3]); FMA2(acc2[i][1], t3, wb[3]);
        }
    }

    float4 bb  = *(const float4*)&bg[c];
    float4 w3a = *(const float4*)&W3[c * 2];
    float4 w3b = *(const float4*)&W3[c * 2 + 4];
    float b30 = b3[0], b31 = b3[1];
#pragma unroll
    for (int i = 0; i < 8; i++) {
        float a0, a1, a2, a3;
        UNPK2(a0, a1, acc2[i][0]);
        UNPK2(a2, a3, acc2[i][1]);
        float vx = fmaxf(a0 + bb.x, 0.f);
        float vy = fmaxf(a1 + bb.y, 0.f);
        float vz = fmaxf(a2 + bb.z, 0.f);
        float vw = fmaxf(a3 + bb.w, 0.f);
        float p0 = vx * w3a.x + vy * w3a.z + vz * w3b.x + vw * w3b.z;
        float p1 = vx * w3a.y + vy * w3a.w + vz * w3b.y + vw * w3b.w;
#pragma unroll
        for (int o = 16; o; o >>= 1) {
            p0 += __shfl_xor_sync(0xffffffffu, p0, o);
            p1 += __shfl_xor_sync(0xffffffffu, p1, o);
        }
        int r = rowBase + warp * 8 + i;
        if (lane == 0 && r < NN) {
            out[r * 2 + 0] = p0 + b30;
            out[r * 2 + 1] = p1 + b31;
        }
    }
}

// ---------------- launch ----------------
extern "C" void kernel_launch(void* const* d_in, const int* in_sizes, int n_in,
                              void* d_out, int out_size) {
    const float* x    = (const float*)d_in[0];
    const int*   ei   = (const int*)  d_in[1];
    const float* ew   = (const float*)d_in[2];
    const float* Wl   = (const float*)d_in[3];
    const float* bl   = (const float*)d_in[4];
    const float* Wr   = (const float*)d_in[5];
    const float* br   = (const float*)d_in[6];
    const float* We   = (const float*)d_in[7];
    const float* att  = (const float*)d_in[8];
    const float* bgat = (const float*)d_in[9];
    const float* W2   = (const float*)d_in[10];
    const float* bgcn = (const float*)d_in[11];
    const float* W3   = (const float*)d_in[12];
    const float* b3   = (const float*)d_in[13];
    float* out = (float*)d_out;

    const int TPB = 256;
    k_setup  <<<HB + LB, TPB>>>(ei, out, x, Wl, bl, Wr, br);
    k_scan   <<<1, 1024>>>();
    k_scatter<<<HB, TPB>>>(ei, ew);
    k_gat    <<<(NN * 32 + TPB - 1) / TPB, TPB>>>(We, att, bgat);
    k_gcn    <<<GCN_BLOCKS + HB, TPB>>>(out);
    k_gemm   <<<(NN + 63) / 64, TPB>>>(W2, bgcn, W3, b3, out);
}

// round 13
// speedup vs baseline: 1.0509x; 1.0509x over previous
#include <cuda_runtime.h>
#include <cuda_fp16.h>

#define NN   100000
#define EE   1600000
#define ET   (EE + NN)     // 1,700,000
#define C    128
#define DIN  6
#define HB   ((ET + 255) / 256)        // 6641 edge blocks
#define LB   ((NN * 64 + 255) / 256)   // 25000 lin blocks

typedef unsigned long long ull;

// ---------------- device scratch ----------------
__device__ __half g_xl[NN * C];    // fp16 feature table (gathered by k_gat)
__device__ float  g_xr[NN * C];    // fp32 (coalesced per-node read)
__device__ __half g_h [NN * C];    // fp16 feature table (gathered by k_gemm)
__device__ float  g_ex[ET];        // CSR-ordered exp(logit)
__device__ float  g_alpha[ET];     // CSR-ordered alpha
__device__ int    g_srca[ET];      // CSR-ordered src
__device__ int    g_eid[ET];       // CSR-ordered original edge id
__device__ float2 g_ef[ET];        // CSR-ordered edge features
__device__ int    g_cnt[NN];       // zero at module load; k_scan re-zeros each call
__device__ int    g_rowptr[NN + 1];
__device__ int    g_cur[NN];

// packed f32x2 helpers (Blackwell)
#define PK2(d, lo, hi) asm("mov.b64 %0, {%1,%2};" : "=l"(d) : "f"(lo), "f"(hi))
#define FMA2(d, a, b)  asm("fma.rn.f32x2 %0, %1, %2, %0;" : "+l"(d) : "l"(a), "l"(b))
#define UNPK2(lo, hi, s) asm("mov.b64 {%0,%1}, %2;" : "=f"(lo), "=f"(hi) : "l"(s))

// load 4 fp16 channels -> float4 (8 bytes)
__device__ __forceinline__ float4 ldh4(const __half* p) {
    uint2 u = *(const uint2*)p;
    __half2 h0, h1;
    *(unsigned*)&h0 = u.x; *(unsigned*)&h1 = u.y;
    float2 f0 = __half22float2(h0), f1 = __half22float2(h1);
    return make_float4(f0.x, f0.y, f1.x, f1.y);
}

// ---------------- K1: fused setup: hist (blocks [0,HB)) + lin (blocks [HB,HB+LB)) ----------------
__global__ void k_setup(const int* __restrict__ ei, float* __restrict__ out,
                        const float* __restrict__ x,
                        const float* __restrict__ Wl, const float* __restrict__ bl,
                        const float* __restrict__ Wr, const float* __restrict__ br) {
    int b = blockIdx.x;
    if (b < HB) {
        int e = b * 256 + threadIdx.x;
        if (e >= ET) return;
        int s, d;
        if (e < EE) { s = ei[e]; d = ei[EE + e]; }
        else        { s = e - EE; d = s; }
        atomicAdd(&g_cnt[d], 1);
        out[NN * 2 + e]      = (float)s;
        out[NN * 2 + ET + e] = (float)d;
    } else {
        int idx = (b - HB) * 256 + threadIdx.x;
        if (idx >= NN * 64) return;
        int n = idx >> 6, cp = (idx & 63) * 2;
        float a0 = bl[cp], a1 = bl[cp + 1];
        float b0 = br[cp], b1 = br[cp + 1];
#pragma unroll
        for (int k = 0; k < DIN; k++) {
            float xv = x[n * DIN + k];
            a0 += xv * Wl[k * C + cp];
            a1 += xv * Wl[k * C + cp + 1];
            b0 += xv * Wr[k * C + cp];
            b1 += xv * Wr[k * C + cp + 1];
        }
        ((__half2*)g_xl)[idx] = __floats2half2_rn(a0, a1);
        *(float2*)&g_xr[n * C + cp] = make_float2(b0, b1);
    }
}

// ---------------- K2: exclusive scan (re-zeros g_cnt for next replay) ----------------
__global__ void k_scan() {
    __shared__ int ssum[1024];
    const int CH = (NN + 1023) / 1024;
    int t = threadIdx.x;
    int beg = t * CH; if (beg > NN) beg = NN;
    int end = beg + CH; if (end > NN) end = NN;
    int s = 0;
    for (int j = beg; j < end; j++) s += g_cnt[j];
    ssum[t] = s;
    __syncthreads();
    for (int off = 1; off < 1024; off <<= 1) {
        int v = (t >= off) ? ssum[t - off] : 0;
        __syncthreads();
        ssum[t] += v;
        __syncthreads();
    }
    int run = t ? ssum[t - 1] : 0;
    for (int j = beg; j < end; j++) {
        int cv = g_cnt[j];
        g_cnt[j] = 0;
        g_rowptr[j] = run;
        g_cur[j]    = run;
        run += cv;
    }
    if (t == 0) g_rowptr[NN] = ET;
}

// ---------------- K3: scatter edges into CSR slots (split arrays) ----------------
__global__ void k_scatter(const int* __restrict__ ei, const float* __restrict__ ew) {
    int e = blockIdx.x * blockDim.x + threadIdx.x;
    if (e >= ET) return;
    int s, d; float e0 = 0.f, e1 = 0.f;
    if (e < EE) {
        s = ei[e]; d = ei[EE + e];
        float2 v = *(const float2*)&ew[2 * e];
        e0 = v.x; e1 = v.y;
    } else { s = e - EE; d = s; }
    int pos = atomicAdd(&g_cur[d], 1);
    g_srca[pos] = s;
    g_eid[pos]  = e;
    g_ef[pos]   = make_float2(e0, e1);
}

// per-lane partial logit for one edge (4 channels)
__device__ __forceinline__ float lane_logit(const float4 a, const float4 xr,
                                            const float2 ef,
                                            const float4 w0, const float4 w1,
                                            const float4 at) {
    float p = 0.f, m;
    m = a.x + xr.x + ef.x * w0.x + ef.y * w1.x; m = m > 0.f ? m : 0.2f * m; p += m * at.x;
    m = a.y + xr.y + ef.x * w0.y + ef.y * w1.y; m = m > 0.f ? m : 0.2f * m; p += m * at.y;
    m = a.z + xr.z + ef.x * w0.z + ef.y * w1.z; m = m > 0.f ? m : 0.2f * m; p += m * at.z;
    m = a.w + xr.w + ef.x * w0.w + ef.y * w1.w; m = m > 0.f ? m : 0.2f * m; p += m * at.w;
    return p;
}

// ---------------- K4: fused GATv2, single gather pass (R5 shape) ----------------
__global__ void k_gat(const float* __restrict__ We, const float* __restrict__ att,
                      const float* __restrict__ bgat, float* __restrict__ out) {
    int node = (blockIdx.x * blockDim.x + threadIdx.x) >> 5;
    int lane = threadIdx.x & 31;
    if (node >= NN) return;
    int c = lane * 4;
    float4 w0 = *(const float4*)&We[c];
    float4 w1 = *(const float4*)&We[C + c];
    float4 at = *(const float4*)&att[c];
    float4 xr = *(const float4*)&g_xr[node * C + c];
    int beg = g_rowptr[node], end = g_rowptr[node + 1];

    float den = 0.f;
    float4 acc = make_float4(0.f, 0.f, 0.f, 0.f);
    int j = beg;
    for (; j + 3 < end; j += 4) {
        int s0 = g_srca[j], s1 = g_srca[j + 1], s2 = g_srca[j + 2], s3 = g_srca[j + 3];
        float2 f0 = g_ef[j], f1 = g_ef[j + 1], f2 = g_ef[j + 2], f3 = g_ef[j + 3];
        const float4 a0 = ldh4(&g_xl[s0 * C + c]);
        const float4 a1 = ldh4(&g_xl[s1 * C + c]);
        const float4 a2 = ldh4(&g_xl[s2 * C + c]);
        const float4 a3 = ldh4(&g_xl[s3 * C + c]);
        float p0 = lane_logit(a0, xr, f0, w0, w1, at);
        float p1 = lane_logit(a1, xr, f1, w0, w1, at);
        float p2 = lane_logit(a2, xr, f2, w0, w1, at);
        float p3 = lane_logit(a3, xr, f3, w0, w1, at);
#pragma unroll
        for (int o = 16; o; o >>= 1) {
            p0 += __shfl_xor_sync(0xffffffffu, p0, o);
            p1 += __shfl_xor_sync(0xffffffffu, p1, o);
            p2 += __shfl_xor_sync(0xffffffffu, p2, o);
            p3 += __shfl_xor_sync(0xffffffffu, p3, o);
        }
        float v0 = __expf(p0), v1 = __expf(p1), v2 = __expf(p2), v3 = __expf(p3);
        if (lane == 0) {
            g_ex[j] = v0; g_ex[j + 1] = v1; g_ex[j + 2] = v2; g_ex[j + 3] = v3;
        }
        den += (v0 + v1) + (v2 + v3);
        acc.x += v0 * a0.x + v1 * a1.x + v2 * a2.x + v3 * a3.x;
        acc.y += v0 * a0.y + v1 * a1.y + v2 * a2.y + v3 * a3.y;
        acc.z += v0 * a0.z + v1 * a1.z + v2 * a2.z + v3 * a3.z;
        acc.w += v0 * a0.w + v1 * a1.w + v2 * a2.w + v3 * a3.w;
    }
    for (; j < end; j++) {
        int s = g_srca[j];
        float2 f = g_ef[j];
        const float4 a = ldh4(&g_xl[s * C + c]);
        float p = lane_logit(a, xr, f, w0, w1, at);
#pragma unroll
        for (int o = 16; o; o >>= 1) p += __shfl_xor_sync(0xffffffffu, p, o);
        float v = __expf(p);
        if (lane == 0) g_ex[j] = v;
        den += v;
        acc.x += v * a.x;
        acc.y += v * a.y;
        acc.z += v * a.z;
        acc.w += v * a.w;
    }
    float inv = 1.f / den;

    // pass B: alpha write-out, lanes parallel over edges
    for (int jj = beg + lane; jj < end; jj += 32) {
        float al = g_ex[jj] * inv;
        g_alpha[jj] = al;
        out[(long long)NN * 2 + 2LL * ET + g_eid[jj]] = al;
    }

    float4 bb = *(const float4*)&bgat[c];
    float hx = fmaxf(acc.x * inv + bb.x, 0.f);
    float hy = fmaxf(acc.y * inv + bb.y, 0.f);
    float hz = fmaxf(acc.z * inv + bb.z, 0.f);
    float hw = fmaxf(acc.w * inv + bb.w, 0.f);
    uint2 hu;
    *(__half2*)&hu.x = __floats2half2_rn(hx, hy);
    *(__half2*)&hu.y = __floats2half2_rn(hz, hw);
    *(uint2*)&g_h[node * C + c] = hu;
}

// ---------------- K5: fused GCN gather + GEMM + head (R5 shape, 256 threads) ----------------
__global__ void k_gemm(const float* __restrict__ W2, const float* __restrict__ bg,
                       const float* __restrict__ W3, const float* __restrict__ b3,
                       float* __restrict__ out) {
    __shared__ float ts[64 * C];
    int lane = threadIdx.x & 31, warp = threadIdx.x >> 5;
    int rowBase = blockIdx.x * 64;
    int c = lane * 4;

    // gather phase: t[node] = sum alpha * h[src]  (deg==1 => norm==alpha)
#pragma unroll
    for (int i = 0; i < 8; i++) {
        int row = warp * 8 + i;
        int node = rowBase + row;
        float4 acc0 = make_float4(0.f, 0.f, 0.f, 0.f);
        float4 acc1 = make_float4(0.f, 0.f, 0.f, 0.f);
        if (node < NN) {
            int beg = g_rowptr[node], end = g_rowptr[node + 1];
            int j = beg;
            for (; j + 1 < end; j += 2) {
                int s0 = g_srca[j], s1 = g_srca[j + 1];
                float al0 = g_alpha[j], al1 = g_alpha[j + 1];
                const float4 h0 = ldh4(&g_h[s0 * C + c]);
                const float4 h1 = ldh4(&g_h[s1 * C + c]);
                acc0.x += al0 * h0.x; acc1.x += al1 * h1.x;
                acc0.y += al0 * h0.y; acc1.y += al1 * h1.y;
                acc0.z += al0 * h0.z; acc1.z += al1 * h1.z;
                acc0.w += al0 * h0.w; acc1.w += al1 * h1.w;
            }
            if (j < end) {
                int s = g_srca[j];
                float al = g_alpha[j];
                const float4 hv = ldh4(&g_h[s * C + c]);
                acc0.x += al * hv.x;
                acc0.y += al * hv.y;
                acc0.z += al * hv.z;
                acc0.w += al * hv.w;
            }
            acc0.x += acc1.x; acc0.y += acc1.y; acc0.z += acc1.z; acc0.w += acc1.w;
        }
        *(float4*)&ts[row * C + c] = acc0;
    }
    __syncthreads();

    // GEMM phase: 8 rows per warp, f32x2 packed FMA
    ull acc2[8][2];
#pragma unroll
    for (int i = 0; i < 8; i++) { acc2[i][0] = 0ull; acc2[i][1] = 0ull; }

    for (int k4 = 0; k4 < C; k4 += 4) {
        ull wa[4], wb[4];
#pragma unroll
        for (int kk = 0; kk < 4; kk++) {
            float4 wv = __ldg((const float4*)&W2[(k4 + kk) * C + c]);
            PK2(wa[kk], wv.x, wv.y);
            PK2(wb[kk], wv.z, wv.w);
        }
#pragma unroll
        for (int i = 0; i < 8; i++) {
            float4 tv = *(const float4*)&ts[(warp * 8 + i) * C + k4];
            ull t0, t1, t2, t3;
            PK2(t0, tv.x, tv.x);
            PK2(t1, tv.y, tv.y);
            PK2(t2, tv.z, tv.z);
            PK2(t3, tv.w, tv.w);
            FMA2(acc2[i][0], t0, wa[0]); FMA2(acc2[i][1], t0, wb[0]);
            FMA2(acc2[i][0], t1, wa[1]); FMA2(acc2[i][1], t1, wb[1]);
            FMA2(acc2[i][0], t2, wa[2]); FMA2(acc2[i][1], t2, wb[2]);
            FMA2(acc2[i][0], t3, wa[3]); FMA2(acc2[i][1], t3, wb[3]);
        }
    }

    float4 bb  = *(const float4*)&bg[c];
    float4 w3a = *(const float4*)&W3[c * 2];
    float4 w3b = *(const float4*)&W3[c * 2 + 4];
    float b30 = b3[0], b31 = b3[1];
#pragma unroll
    for (int i = 0; i < 8; i++) {
        float a0, a1, a2, a3;
        UNPK2(a0, a1, acc2[i][0]);
        UNPK2(a2, a3, acc2[i][1]);
        float vx = fmaxf(a0 + bb.x, 0.f);
        float vy = fmaxf(a1 + bb.y, 0.f);
        float vz = fmaxf(a2 + bb.z, 0.f);
        float vw = fmaxf(a3 + bb.w, 0.f);
        float p0 = vx * w3a.x + vy * w3a.z + vz * w3b.x + vw * w3b.z;
        float p1 = vx * w3a.y + vy * w3a.w + vz * w3b.y + vw * w3b.w;
#pragma unroll
        for (int o = 16; o; o >>= 1) {
            p0 += __shfl_xor_sync(0xffffffffu, p0, o);
            p1 += __shfl_xor_sync(0xffffffffu, p1, o);
        }
        int r = rowBase + warp * 8 + i;
        if (lane == 0 && r < NN) {
            out[r * 2 + 0] = p0 + b30;
            out[r * 2 + 1] = p1 + b31;
        }
    }
}

// ---------------- launch ----------------
extern "C" void kernel_launch(void* const* d_in, const int* in_sizes, int n_in,
                              void* d_out, int out_size) {
    const float* x    = (const float*)d_in[0];
    const int*   ei   = (const int*)  d_in[1];
    const float* ew   = (const float*)d_in[2];
    const float* Wl   = (const float*)d_in[3];
    const float* bl   = (const float*)d_in[4];
    const float* Wr   = (const float*)d_in[5];
    const float* br   = (const float*)d_in[6];
    const float* We   = (const float*)d_in[7];
    const float* att  = (const float*)d_in[8];
    const float* bgat = (const float*)d_in[9];
    const float* W2   = (const float*)d_in[10];
    const float* bgcn = (const float*)d_in[11];
    const float* W3   = (const float*)d_in[12];
    const float* b3   = (const float*)d_in[13];
    float* out = (float*)d_out;

    const int TPB = 256;
    k_setup  <<<HB + LB, TPB>>>(ei, out, x, Wl, bl, Wr, br);
    k_scan   <<<1, 1024>>>();
    k_scatter<<<HB, TPB>>>(ei, ew);
    k_gat    <<<(NN * 32 + TPB - 1) / TPB, TPB>>>(We, att, bgat, out);
    k_gemm   <<<(NN + 63) / 64, TPB>>>(W2, bgcn, W3, b3, out);
}

// round 14
// speedup vs baseline: 1.0570x; 1.0057x over previous
#include <cuda_runtime.h>
#include <cuda_fp16.h>

#define NN   100000
#define EE   1600000
#define ET   (EE + NN)     // 1,700,000
#define C    128
#define DIN  6
#define HB   ((ET + 255) / 256)        // 6641 edge blocks
#define LB   ((NN * 64 + 255) / 256)   // 25000 lin blocks

typedef unsigned long long ull;

// ---------------- device scratch ----------------
__device__ __half g_xl[NN * C];
__device__ float  g_xr[NN * C];
__device__ __half g_h [NN * C];
__device__ float  g_ex[ET];
__device__ float  g_alpha[ET];
__device__ int    g_srca[ET];
__device__ int    g_eid[ET];
__device__ float2 g_ef[ET];
__device__ int    g_cnt[NN];       // zero at module load; k_scan re-zeros each call
__device__ int    g_rowptr[NN + 1];
__device__ int    g_cur[NN];

// packed f32x2 helpers (Blackwell)
#define PK2(d, lo, hi)    asm("mov.b64 %0, {%1,%2};" : "=l"(d) : "f"(lo), "f"(hi))
#define UNPK2(lo, hi, s)  asm("mov.b64 {%0,%1}, %2;" : "=f"(lo), "=f"(hi) : "l"(s))
#define ADD2(d, a, b)     asm("add.rn.f32x2 %0, %1, %2;" : "=l"(d) : "l"(a), "l"(b))
#define MUL2(d, a, b)     asm("mul.rn.f32x2 %0, %1, %2;" : "=l"(d) : "l"(a), "l"(b))
#define FMA2D(d, a, b, c) asm("fma.rn.f32x2 %0, %1, %2, %3;" : "=l"(d) : "l"(a), "l"(b), "l"(c))
#define FMA2(d, a, b)     asm("fma.rn.f32x2 %0, %1, %2, %0;" : "+l"(d) : "l"(a), "l"(b))
#define AND64(d, a)       asm("and.b64 %0, %1, 0x7FFFFFFF7FFFFFFF;" : "=l"(d) : "l"(a))

// load 4 fp16 channels -> float4 (8 bytes)
__device__ __forceinline__ float4 ldh4(const __half* p) {
    uint2 u = *(const uint2*)p;
    __half2 h0, h1;
    *(unsigned*)&h0 = u.x; *(unsigned*)&h1 = u.y;
    float2 f0 = __half22float2(h0), f1 = __half22float2(h1);
    return make_float4(f0.x, f0.y, f1.x, f1.y);
}

// ---------------- K1: fused setup: hist (blocks [0,HB)) + lin (blocks [HB,HB+LB)) ----------------
__global__ void k_setup(const int* __restrict__ ei, float* __restrict__ out,
                        const float* __restrict__ x,
                        const float* __restrict__ Wl, const float* __restrict__ bl,
                        const float* __restrict__ Wr, const float* __restrict__ br) {
    int b = blockIdx.x;
    if (b < HB) {
        int e = b * 256 + threadIdx.x;
        if (e >= ET) return;
        int s, d;
        if (e < EE) { s = ei[e]; d = ei[EE + e]; }
        else        { s = e - EE; d = s; }
        atomicAdd(&g_cnt[d], 1);
        out[NN * 2 + e]      = (float)s;
        out[NN * 2 + ET + e] = (float)d;
    } else {
        int idx = (b - HB) * 256 + threadIdx.x;
        if (idx >= NN * 64) return;
        int n = idx >> 6, cp = (idx & 63) * 2;
        float a0 = bl[cp], a1 = bl[cp + 1];
        float b0 = br[cp], b1 = br[cp + 1];
#pragma unroll
        for (int k = 0; k < DIN; k++) {
            float xv = x[n * DIN + k];
            a0 += xv * Wl[k * C + cp];
            a1 += xv * Wl[k * C + cp + 1];
            b0 += xv * Wr[k * C + cp];
            b1 += xv * Wr[k * C + cp + 1];
        }
        ((__half2*)g_xl)[idx] = __floats2half2_rn(a0, a1);
        *(float2*)&g_xr[n * C + cp] = make_float2(b0, b1);
    }
}

// ---------------- K2: exclusive scan (re-zeros g_cnt for next replay) ----------------
__global__ void k_scan() {
    __shared__ int ssum[1024];
    const int CH = (NN + 1023) / 1024;
    int t = threadIdx.x;
    int beg = t * CH; if (beg > NN) beg = NN;
    int end = beg + CH; if (end > NN) end = NN;
    int s = 0;
    for (int j = beg; j < end; j++) s += g_cnt[j];
    ssum[t] = s;
    __syncthreads();
    for (int off = 1; off < 1024; off <<= 1) {
        int v = (t >= off) ? ssum[t - off] : 0;
        __syncthreads();
        ssum[t] += v;
        __syncthreads();
    }
    int run = t ? ssum[t - 1] : 0;
    for (int j = beg; j < end; j++) {
        int cv = g_cnt[j];
        g_cnt[j] = 0;
        g_rowptr[j] = run;
        g_cur[j]    = run;
        run += cv;
    }
    if (t == 0) g_rowptr[NN] = ET;
}

// ---------------- K3: scatter edges into CSR slots ----------------
__global__ void k_scatter(const int* __restrict__ ei, const float* __restrict__ ew) {
    int e = blockIdx.x * blockDim.x + threadIdx.x;
    if (e >= ET) return;
    int s, d; float e0 = 0.f, e1 = 0.f;
    if (e < EE) {
        s = ei[e]; d = ei[EE + e];
        float2 v = *(const float2*)&ew[2 * e];
        e0 = v.x; e1 = v.y;
    } else { s = e - EE; d = s; }
    int pos = atomicAdd(&g_cur[d], 1);
    g_srca[pos] = s;
    g_eid[pos]  = e;
    g_ef[pos]   = make_float2(e0, e1);
}

// packed logit for one edge's 4 channels on this lane; also emits packed a0,a1 for reuse
__device__ __forceinline__ float lane_logit_pk(uint2 u,
                                               ull xr0, ull xr1,
                                               ull e0p, ull e1p,
                                               ull w00, ull w01, ull w10, ull w11,
                                               ull at0, ull at1,
                                               ull c04, ull c06,
                                               ull& a0, ull& a1) {
    float2 f01 = __half22float2(*(__half2*)&u.x);
    float2 f23 = __half22float2(*(__half2*)&u.y);
    PK2(a0, f01.x, f01.y);
    PK2(a1, f23.x, f23.y);
    ull m, am, t, r, pacc;
    ADD2(m, a0, xr0);
    FMA2D(m, e0p, w00, m);
    FMA2D(m, e1p, w10, m);
    AND64(am, m);
    MUL2(t, am, c04);
    FMA2D(r, m, c06, t);              // leaky_relu(m, 0.2) = 0.6m + 0.4|m|
    MUL2(pacc, r, at0);
    ADD2(m, a1, xr1);
    FMA2D(m, e0p, w01, m);
    FMA2D(m, e1p, w11, m);
    AND64(am, m);
    MUL2(t, am, c04);
    FMA2D(r, m, c06, t);
    FMA2(pacc, r, at1);
    float plo, phi;
    UNPK2(plo, phi, pacc);
    return plo + phi;
}

// ---------------- K4: fused GATv2, single gather pass, packed f32x2 math ----------------
__global__ void __launch_bounds__(256, 4)
k_gat(const float* __restrict__ We, const float* __restrict__ att,
      const float* __restrict__ bgat, float* __restrict__ out) {
    int node = (blockIdx.x * blockDim.x + threadIdx.x) >> 5;
    int lane = threadIdx.x & 31;
    if (node >= NN) return;
    int c = lane * 4;

    ull w00, w01, w10, w11, at0, at1, xr0, xr1, c04, c06;
    {
        float4 A = *(const float4*)&We[c];
        PK2(w00, A.x, A.y); PK2(w01, A.z, A.w);
        A = *(const float4*)&We[C + c];
        PK2(w10, A.x, A.y); PK2(w11, A.z, A.w);
        A = *(const float4*)&att[c];
        PK2(at0, A.x, A.y); PK2(at1, A.z, A.w);
        A = *(const float4*)&g_xr[node * C + c];
        PK2(xr0, A.x, A.y); PK2(xr1, A.z, A.w);
    }
    PK2(c04, 0.4f, 0.4f);
    PK2(c06, 0.6f, 0.6f);

    int beg = g_rowptr[node], end = g_rowptr[node + 1];
    float den = 0.f;
    ull acc0 = 0ull, acc1 = 0ull;     // packed fp32 accumulators (0.0,0.0)

    int j = beg;
    for (; j + 3 < end; j += 4) {
        int s0 = g_srca[j], s1 = g_srca[j + 1], s2 = g_srca[j + 2], s3 = g_srca[j + 3];
        float2 f0 = g_ef[j], f1 = g_ef[j + 1], f2 = g_ef[j + 2], f3 = g_ef[j + 3];
        uint2 u0 = *(const uint2*)&g_xl[s0 * C + c];
        uint2 u1 = *(const uint2*)&g_xl[s1 * C + c];
        uint2 u2 = *(const uint2*)&g_xl[s2 * C + c];
        uint2 u3 = *(const uint2*)&g_xl[s3 * C + c];
        ull e00, e01, e10, e11, e20, e21, e30, e31;
        PK2(e00, f0.x, f0.x); PK2(e01, f0.y, f0.y);
        PK2(e10, f1.x, f1.x); PK2(e11, f1.y, f1.y);
        PK2(e20, f2.x, f2.x); PK2(e21, f2.y, f2.y);
        PK2(e30, f3.x, f3.x); PK2(e31, f3.y, f3.y);
        ull a00, a01, a10, a11, a20, a21, a30, a31;
        float p0 = lane_logit_pk(u0, xr0, xr1, e00, e01, w00, w01, w10, w11, at0, at1, c04, c06, a00, a01);
        float p1 = lane_logit_pk(u1, xr0, xr1, e10, e11, w00, w01, w10, w11, at0, at1, c04, c06, a10, a11);
        float p2 = lane_logit_pk(u2, xr0, xr1, e20, e21, w00, w01, w10, w11, at0, at1, c04, c06, a20, a21);
        float p3 = lane_logit_pk(u3, xr0, xr1, e30, e31, w00, w01, w10, w11, at0, at1, c04, c06, a30, a31);
#pragma unroll
        for (int o = 16; o; o >>= 1) {
            p0 += __shfl_xor_sync(0xffffffffu, p0, o);
            p1 += __shfl_xor_sync(0xffffffffu, p1, o);
            p2 += __shfl_xor_sync(0xffffffffu, p2, o);
            p3 += __shfl_xor_sync(0xffffffffu, p3, o);
        }
        float v0 = __expf(p0), v1 = __expf(p1), v2 = __expf(p2), v3 = __expf(p3);
        if (lane == 0) {
            g_ex[j] = v0; g_ex[j + 1] = v1; g_ex[j + 2] = v2; g_ex[j + 3] = v3;
        }
        den += (v0 + v1) + (v2 + v3);
        ull vp;
        PK2(vp, v0, v0); FMA2(acc0, vp, a00); FMA2(acc1, vp, a01);
        PK2(vp, v1, v1); FMA2(acc0, vp, a10); FMA2(acc1, vp, a11);
        PK2(vp, v2, v2); FMA2(acc0, vp, a20); FMA2(acc1, vp, a21);
        PK2(vp, v3, v3); FMA2(acc0, vp, a30); FMA2(acc1, vp, a31);
    }
    for (; j < end; j++) {
        int s = g_srca[j];
        float2 f = g_ef[j];
        uint2 u = *(const uint2*)&g_xl[s * C + c];
        ull e0p, e1p, a0, a1;
        PK2(e0p, f.x, f.x); PK2(e1p, f.y, f.y);
        float p = lane_logit_pk(u, xr0, xr1, e0p, e1p, w00, w01, w10, w11, at0, at1, c04, c06, a0, a1);
#pragma unroll
        for (int o = 16; o; o >>= 1) p += __shfl_xor_sync(0xffffffffu, p, o);
        float v = __expf(p);
        if (lane == 0) g_ex[j] = v;
        den += v;
        ull vp;
        PK2(vp, v, v);
        FMA2(acc0, vp, a0); FMA2(acc1, vp, a1);
    }
    float inv = 1.f / den;

    // pass B: alpha write-out, lanes parallel over edges
    for (int jj = beg + lane; jj < end; jj += 32) {
        float al = g_ex[jj] * inv;
        g_alpha[jj] = al;
        out[(long long)NN * 2 + 2LL * ET + g_eid[jj]] = al;
    }

    float ax, ay, az, aw;
    UNPK2(ax, ay, acc0);
    UNPK2(az, aw, acc1);
    float4 bb = *(const float4*)&bgat[c];
    float hx = fmaxf(ax * inv + bb.x, 0.f);
    float hy = fmaxf(ay * inv + bb.y, 0.f);
    float hz = fmaxf(az * inv + bb.z, 0.f);
    float hw = fmaxf(aw * inv + bb.w, 0.f);
    uint2 hu;
    *(__half2*)&hu.x = __floats2half2_rn(hx, hy);
    *(__half2*)&hu.y = __floats2half2_rn(hz, hw);
    *(uint2*)&g_h[node * C + c] = hu;
}

// ---------------- K5: fused GCN gather + GEMM + head (32 rows, 128 threads, 3125 blocks) ----------------
__global__ void __launch_bounds__(128)
k_gemm(const float* __restrict__ W2, const float* __restrict__ bg,
       const float* __restrict__ W3, const float* __restrict__ b3,
       float* __restrict__ out) {
    __shared__ float ts[32 * C];
    int lane = threadIdx.x & 31, warp = threadIdx.x >> 5;   // 4 warps
    int rowBase = blockIdx.x * 32;
    int c = lane * 4;

    // gather phase: each warp handles 8 rows; t[node] = sum alpha * h[src], unroll 4
#pragma unroll
    for (int i = 0; i < 8; i++) {
        int row = warp * 8 + i;
        int node = rowBase + row;
        float4 acc0 = make_float4(0.f, 0.f, 0.f, 0.f);
        float4 acc1 = make_float4(0.f, 0.f, 0.f, 0.f);
        if (node < NN) {
            int beg = g_rowptr[node], end = g_rowptr[node + 1];
            int j = beg;
            for (; j + 3 < end; j += 4) {
                int s0 = g_srca[j], s1 = g_srca[j + 1], s2 = g_srca[j + 2], s3 = g_srca[j + 3];
                float al0 = g_alpha[j],     al1 = g_alpha[j + 1];
                float al2 = g_alpha[j + 2], al3 = g_alpha[j + 3];
                const float4 h0 = ldh4(&g_h[s0 * C + c]);
                const float4 h1 = ldh4(&g_h[s1 * C + c]);
                const float4 h2 = ldh4(&g_h[s2 * C + c]);
                const float4 h3 = ldh4(&g_h[s3 * C + c]);
                acc0.x += al0 * h0.x + al2 * h2.x; acc1.x += al1 * h1.x + al3 * h3.x;
                acc0.y += al0 * h0.y + al2 * h2.y; acc1.y += al1 * h1.y + al3 * h3.y;
                acc0.z += al0 * h0.z + al2 * h2.z; acc1.z += al1 * h1.z + al3 * h3.z;
                acc0.w += al0 * h0.w + al2 * h2.w; acc1.w += al1 * h1.w + al3 * h3.w;
            }
            for (; j < end; j++) {
                int s = g_srca[j];
                float al = g_alpha[j];
                const float4 hv = ldh4(&g_h[s * C + c]);
                acc0.x += al * hv.x;
                acc0.y += al * hv.y;
                acc0.z += al * hv.z;
                acc0.w += al * hv.w;
            }
            acc0.x += acc1.x; acc0.y += acc1.y; acc0.z += acc1.z; acc0.w += acc1.w;
        }
        *(float4*)&ts[row * C + c] = acc0;
    }
    __syncthreads();

    // GEMM phase: 8 rows per warp, f32x2 packed FMA
    ull acc2[8][2];
#pragma unroll
    for (int i = 0; i < 8; i++) { acc2[i][0] = 0ull; acc2[i][1] = 0ull; }

    for (int k4 = 0; k4 < C; k4 += 4) {
        ull wa[4], wb[4];
#pragma unroll
        for (int kk = 0; kk < 4; kk++) {
            float4 wv = __ldg((const float4*)&W2[(k4 + kk) * C + c]);
            PK2(wa[kk], wv.x, wv.y);
            PK2(wb[kk], wv.z, wv.w);
        }
#pragma unroll
        for (int i = 0; i < 8; i++) {
            float4 tv = *(const float4*)&ts[(warp * 8 + i) * C + k4];
            ull t0, t1, t2, t3;
            PK2(t0, tv.x, tv.x);
            PK2(t1, tv.y, tv.y);
            PK2(t2, tv.z, tv.z);
            PK2(t3, tv.w, tv.w);
            FMA2(acc2[i][0], t0, wa[0]); FMA2(acc2[i][1], t0, wb[0]);
            FMA2(acc2[i][0], t1, wa[1]); FMA2(acc2[i][1], t1, wb[1]);
            FMA2(acc2[i][0], t2, wa[2]); FMA2(acc2[i][1], t2, wb[2]);
            FMA2(acc2[i][0], t3, wa[3]); FMA2(acc2[i][1], t3, wb[3]);
        }
    }

    float4 bb  = *(const float4*)&bg[c];
    float4 w3a = *(const float4*)&W3[c * 2];
    float4 w3b = *(const float4*)&W3[c * 2 + 4];
    float b30 = b3[0], b31 = b3[1];
#pragma unroll
    for (int i = 0; i < 8; i++) {
        float a0, a1, a2, a3;
        UNPK2(a0, a1, acc2[i][0]);
        UNPK2(a2, a3, acc2[i][1]);
        float vx = fmaxf(a0 + bb.x, 0.f);
        float vy = fmaxf(a1 + bb.y, 0.f);
        float vz = fmaxf(a2 + bb.z, 0.f);
        float vw = fmaxf(a3 + bb.w, 0.f);
        float p0 = vx * w3a.x + vy * w3a.z + vz * w3b.x + vw * w3b.z;
        float p1 = vx * w3a.y + vy * w3a.w + vz * w3b.y + vw * w3b.w;
#pragma unroll
        for (int o = 16; o; o >>= 1) {
            p0 += __shfl_xor_sync(0xffffffffu, p0, o);
            p1 += __shfl_xor_sync(0xffffffffu, p1, o);
        }
        int r = rowBase + warp * 8 + i;
        if (lane == 0 && r < NN) {
            out[r * 2 + 0] = p0 + b30;
            out[r * 2 + 1] = p1 + b31;
        }
    }
}

// ---------------- launch ----------------
extern "C" void kernel_launch(void* const* d_in, const int* in_sizes, int n_in,
                              void* d_out, int out_size) {
    const float* x    = (const float*)d_in[0];
    const int*   ei   = (const int*)  d_in[1];
    const float* ew   = (const float*)d_in[2];
    const float* Wl   = (const float*)d_in[3];
    const float* bl   = (const float*)d_in[4];
    const float* Wr   = (const float*)d_in[5];
    const float* br   = (const float*)d_in[6];
    const float* We   = (const float*)d_in[7];
    const float* att  = (const float*)d_in[8];
    const float* bgat = (const float*)d_in[9];
    const float* W2   = (const float*)d_in[10];
    const float* bgcn = (const float*)d_in[11];
    const float* W3   = (const float*)d_in[12];
    const float* b3   = (const float*)d_in[13];
    float* out = (float*)d_out;

    const int TPB = 256;
    k_setup  <<<HB + LB, TPB>>>(ei, out, x, Wl, bl, Wr, br);
    k_scan   <<<1, 1024>>>();
    k_scatter<<<HB, TPB>>>(ei, ew);
    k_gat    <<<(NN * 32 + TPB - 1) / TPB, TPB>>>(We, att, bgat, out);
    k_gemm   <<<(NN + 31) / 32, 128>>>(W2, bgcn, W3, b3, out);
}

// round 15
// speedup vs baseline: 1.0993x; 1.0400x over previous
#include <cuda_runtime.h>
#include <cuda_fp16.h>

#define NN   100000
#define EE   1600000
#define ET   (EE + NN)     // 1,700,000
#define C    128
#define DIN  6

typedef unsigned long long ull;

// ---------------- device scratch ----------------
__device__ __half g_xl[NN * C];    // fp16 feature table (gathered by k_gat)
__device__ float  g_xr[NN * C];    // fp32 (coalesced per-node read)
__device__ __half g_h [NN * C];    // fp16 feature table (gathered by k_gemm)
__device__ float  g_ex[ET];        // CSR-ordered exp(logit)
__device__ float  g_alpha[ET];     // CSR-ordered alpha
__device__ int    g_srca[ET];      // CSR-ordered src
__device__ int    g_eid[ET];       // CSR-ordered original edge id
__device__ float2 g_ef[ET];        // CSR-ordered edge features
__device__ int    g_cnt[NN];
__device__ int    g_rowptr[NN + 1];
__device__ int    g_cur[NN];

// packed f32x2 helpers (Blackwell)
#define PK2(d, lo, hi)    asm("mov.b64 %0, {%1,%2};" : "=l"(d) : "f"(lo), "f"(hi))
#define UNPK2(lo, hi, s)  asm("mov.b64 {%0,%1}, %2;" : "=f"(lo), "=f"(hi) : "l"(s))
#define ADD2(d, a, b)     asm("add.rn.f32x2 %0, %1, %2;" : "=l"(d) : "l"(a), "l"(b))
#define MUL2(d, a, b)     asm("mul.rn.f32x2 %0, %1, %2;" : "=l"(d) : "l"(a), "l"(b))
#define FMA2D(d, a, b, c) asm("fma.rn.f32x2 %0, %1, %2, %3;" : "=l"(d) : "l"(a), "l"(b), "l"(c))
#define FMA2(d, a, b)     asm("fma.rn.f32x2 %0, %1, %2, %0;" : "+l"(d) : "l"(a), "l"(b))
#define AND64(d, a)       asm("and.b64 %0, %1, 0x7FFFFFFF7FFFFFFF;" : "=l"(d) : "l"(a))

// load 4 fp16 channels -> float4 (8 bytes)
__device__ __forceinline__ float4 ldh4(const __half* p) {
    uint2 u = *(const uint2*)p;
    __half2 h0, h1;
    *(unsigned*)&h0 = u.x; *(unsigned*)&h1 = u.y;
    float2 f0 = __half22float2(h0), f1 = __half22float2(h1);
    return make_float4(f0.x, f0.y, f1.x, f1.y);
}

// ---------------- K0 ----------------
__global__ void k_zerocnt() {
    int i = blockIdx.x * blockDim.x + threadIdx.x;
    if (i < NN) g_cnt[i] = 0;
}

// ---------------- K1: histogram + src/dst stack output ----------------
__global__ void k_hist(const int* __restrict__ ei, float* __restrict__ out) {
    int e = blockIdx.x * blockDim.x + threadIdx.x;
    if (e >= ET) return;
    int s, d;
    if (e < EE) { s = ei[e]; d = ei[EE + e]; }
    else        { s = e - EE; d = s; }
    atomicAdd(&g_cnt[d], 1);
    out[NN * 2 + e]      = (float)s;
    out[NN * 2 + ET + e] = (float)d;
}

// ---------------- K2: exclusive scan ----------------
__global__ void k_scan() {
    __shared__ int ssum[1024];
    const int CH = (NN + 1023) / 1024;
    int t = threadIdx.x;
    int beg = t * CH; if (beg > NN) beg = NN;
    int end = beg + CH; if (end > NN) end = NN;
    int s = 0;
    for (int j = beg; j < end; j++) s += g_cnt[j];
    ssum[t] = s;
    __syncthreads();
    for (int off = 1; off < 1024; off <<= 1) {
        int v = (t >= off) ? ssum[t - off] : 0;
        __syncthreads();
        ssum[t] += v;
        __syncthreads();
    }
    int run = t ? ssum[t - 1] : 0;
    for (int j = beg; j < end; j++) {
        g_rowptr[j] = run;
        g_cur[j]    = run;
        run += g_cnt[j];
    }
    if (t == 0) g_rowptr[NN] = ET;
}

// ---------------- K3: scatter edges into CSR slots (split arrays) ----------------
__global__ void k_scatter(const int* __restrict__ ei, const float* __restrict__ ew) {
    int e = blockIdx.x * blockDim.x + threadIdx.x;
    if (e >= ET) return;
    int s, d; float e0 = 0.f, e1 = 0.f;
    if (e < EE) {
        s = ei[e]; d = ei[EE + e];
        float2 v = *(const float2*)&ew[2 * e];
        e0 = v.x; e1 = v.y;
    } else { s = e - EE; d = s; }
    int pos = atomicAdd(&g_cur[d], 1);
    g_srca[pos] = s;
    g_eid[pos]  = e;
    g_ef[pos]   = make_float2(e0, e1);
}

// ---------------- K4: xl = fp16(x@Wl + bl) ; xr = x@Wr + br ----------------
__global__ void k_lin(const float* __restrict__ x,
                      const float* __restrict__ Wl, const float* __restrict__ bl,
                      const float* __restrict__ Wr, const float* __restrict__ br) {
    int idx = blockIdx.x * blockDim.x + threadIdx.x;
    if (idx >= NN * 64) return;
    int n = idx >> 6, cp = (idx & 63) * 2;
    float a0 = bl[cp], a1 = bl[cp + 1];
    float b0 = br[cp], b1 = br[cp + 1];
#pragma unroll
    for (int k = 0; k < DIN; k++) {
        float xv = x[n * DIN + k];
        a0 += xv * Wl[k * C + cp];
        a1 += xv * Wl[k * C + cp + 1];
        b0 += xv * Wr[k * C + cp];
        b1 += xv * Wr[k * C + cp + 1];
    }
    ((__half2*)g_xl)[idx] = __floats2half2_rn(a0, a1);
    *(float2*)&g_xr[n * C + cp] = make_float2(b0, b1);
}

// packed logit for one edge's 4 channels on this lane; also emits packed a0,a1 for reuse
__device__ __forceinline__ float lane_logit_pk(uint2 u,
                                               ull xr0, ull xr1,
                                               ull e0p, ull e1p,
                                               ull w00, ull w01, ull w10, ull w11,
                                               ull at0, ull at1,
                                               ull c04, ull c06,
                                               ull& a0, ull& a1) {
    float2 f01 = __half22float2(*(__half2*)&u.x);
    float2 f23 = __half22float2(*(__half2*)&u.y);
    PK2(a0, f01.x, f01.y);
    PK2(a1, f23.x, f23.y);
    ull m, am, t, r, pacc;
    ADD2(m, a0, xr0);
    FMA2D(m, e0p, w00, m);
    FMA2D(m, e1p, w10, m);
    AND64(am, m);
    MUL2(t, am, c04);
    FMA2D(r, m, c06, t);              // leaky_relu(m, 0.2) = 0.6m + 0.4|m|
    MUL2(pacc, r, at0);
    ADD2(m, a1, xr1);
    FMA2D(m, e0p, w01, m);
    FMA2D(m, e1p, w11, m);
    AND64(am, m);
    MUL2(t, am, c04);
    FMA2D(r, m, c06, t);
    FMA2(pacc, r, at1);
    float plo, phi;
    UNPK2(plo, phi, pacc);
    return plo + phi;
}

// ---------------- K5: fused GATv2, single gather pass, packed f32x2 math ----------------
__global__ void __launch_bounds__(256, 4)
k_gat(const float* __restrict__ We, const float* __restrict__ att,
      const float* __restrict__ bgat, float* __restrict__ out) {
    int node = (blockIdx.x * blockDim.x + threadIdx.x) >> 5;
    int lane = threadIdx.x & 31;
    if (node >= NN) return;
    int c = lane * 4;

    ull w00, w01, w10, w11, at0, at1, xr0, xr1, c04, c06;
    {
        float4 A = *(const float4*)&We[c];
        PK2(w00, A.x, A.y); PK2(w01, A.z, A.w);
        A = *(const float4*)&We[C + c];
        PK2(w10, A.x, A.y); PK2(w11, A.z, A.w);
        A = *(const float4*)&att[c];
        PK2(at0, A.x, A.y); PK2(at1, A.z, A.w);
        A = *(const float4*)&g_xr[node * C + c];
        PK2(xr0, A.x, A.y); PK2(xr1, A.z, A.w);
    }
    PK2(c04, 0.4f, 0.4f);
    PK2(c06, 0.6f, 0.6f);

    int beg = g_rowptr[node], end = g_rowptr[node + 1];
    float den = 0.f;
    ull acc0 = 0ull, acc1 = 0ull;     // packed fp32 accumulators (0.0,0.0)

    int j = beg;
    for (; j + 3 < end; j += 4) {
        int s0 = g_srca[j], s1 = g_srca[j + 1], s2 = g_srca[j + 2], s3 = g_srca[j + 3];
        float2 f0 = g_ef[j], f1 = g_ef[j + 1], f2 = g_ef[j + 2], f3 = g_ef[j + 3];
        uint2 u0 = *(const uint2*)&g_xl[s0 * C + c];
        uint2 u1 = *(const uint2*)&g_xl[s1 * C + c];
        uint2 u2 = *(const uint2*)&g_xl[s2 * C + c];
        uint2 u3 = *(const uint2*)&g_xl[s3 * C + c];
        ull e00, e01, e10, e11, e20, e21, e30, e31;
        PK2(e00, f0.x, f0.x); PK2(e01, f0.y, f0.y);
        PK2(e10, f1.x, f1.x); PK2(e11, f1.y, f1.y);
        PK2(e20, f2.x, f2.x); PK2(e21, f2.y, f2.y);
        PK2(e30, f3.x, f3.x); PK2(e31, f3.y, f3.y);
        ull a00, a01, a10, a11, a20, a21, a30, a31;
        float p0 = lane_logit_pk(u0, xr0, xr1, e00, e01, w00, w01, w10, w11, at0, at1, c04, c06, a00, a01);
        float p1 = lane_logit_pk(u1, xr0, xr1, e10, e11, w00, w01, w10, w11, at0, at1, c04, c06, a10, a11);
        float p2 = lane_logit_pk(u2, xr0, xr1, e20, e21, w00, w01, w10, w11, at0, at1, c04, c06, a20, a21);
        float p3 = lane_logit_pk(u3, xr0, xr1, e30, e31, w00, w01, w10, w11, at0, at1, c04, c06, a30, a31);
#pragma unroll
        for (int o = 16; o; o >>= 1) {
            p0 += __shfl_xor_sync(0xffffffffu, p0, o);
            p1 += __shfl_xor_sync(0xffffffffu, p1, o);
            p2 += __shfl_xor_sync(0xffffffffu, p2, o);
            p3 += __shfl_xor_sync(0xffffffffu, p3, o);
        }
        float v0 = __expf(p0), v1 = __expf(p1), v2 = __expf(p2), v3 = __expf(p3);
        if (lane == 0) {
            g_ex[j] = v0; g_ex[j + 1] = v1; g_ex[j + 2] = v2; g_ex[j + 3] = v3;
        }
        den += (v0 + v1) + (v2 + v3);
        ull vp;
        PK2(vp, v0, v0); FMA2(acc0, vp, a00); FMA2(acc1, vp, a01);
        PK2(vp, v1, v1); FMA2(acc0, vp, a10); FMA2(acc1, vp, a11);
        PK2(vp, v2, v2); FMA2(acc0, vp, a20); FMA2(acc1, vp, a21);
        PK2(vp, v3, v3); FMA2(acc0, vp, a30); FMA2(acc1, vp, a31);
    }
    for (; j < end; j++) {
        int s = g_srca[j];
        float2 f = g_ef[j];
        uint2 u = *(const uint2*)&g_xl[s * C + c];
        ull e0p, e1p, a0, a1;
        PK2(e0p, f.x, f.x); PK2(e1p, f.y, f.y);
        float p = lane_logit_pk(u, xr0, xr1, e0p, e1p, w00, w01, w10, w11, at0, at1, c04, c06, a0, a1);
#pragma unroll
        for (int o = 16; o; o >>= 1) p += __shfl_xor_sync(0xffffffffu, p, o);
        float v = __expf(p);
        if (lane == 0) g_ex[j] = v;
        den += v;
        ull vp;
        PK2(vp, v, v);
        FMA2(acc0, vp, a0); FMA2(acc1, vp, a1);
    }
    float inv = 1.f / den;

    // pass B: alpha write-out, lanes parallel over edges
    for (int jj = beg + lane; jj < end; jj += 32) {
        float al = g_ex[jj] * inv;
        g_alpha[jj] = al;
        out[(long long)NN * 2 + 2LL * ET + g_eid[jj]] = al;
    }

    float ax, ay, az, aw;
    UNPK2(ax, ay, acc0);
    UNPK2(az, aw, acc1);
    float4 bb = *(const float4*)&bgat[c];
    float hx = fmaxf(ax * inv + bb.x, 0.f);
    float hy = fmaxf(ay * inv + bb.y, 0.f);
    float hz = fmaxf(az * inv + bb.z, 0.f);
    float hw = fmaxf(aw * inv + bb.w, 0.f);
    uint2 hu;
    *(__half2*)&hu.x = __floats2half2_rn(hx, hy);
    *(__half2*)&hu.y = __floats2half2_rn(hz, hw);
    *(uint2*)&g_h[node * C + c] = hu;
}

// ---------------- K6: fused GCN gather + GEMM + head (R5 shape: 256 threads, 64 rows) ----------------
__global__ void k_gemm(const float* __restrict__ W2, const float* __restrict__ bg,
                       const float* __restrict__ W3, const float* __restrict__ b3,
                       float* __restrict__ out) {
    __shared__ float ts[64 * C];
    int lane = threadIdx.x & 31, warp = threadIdx.x >> 5;
    int rowBase = blockIdx.x * 64;
    int c = lane * 4;

    // gather phase: t[node] = sum alpha * h[src]  (deg==1 => norm==alpha)
#pragma unroll
    for (int i = 0; i < 8; i++) {
        int row = warp * 8 + i;
        int node = rowBase + row;
        float4 acc0 = make_float4(0.f, 0.f, 0.f, 0.f);
        float4 acc1 = make_float4(0.f, 0.f, 0.f, 0.f);
        if (node < NN) {
            int beg = g_rowptr[node], end = g_rowptr[node + 1];
            int j = beg;
            for (; j + 1 < end; j += 2) {
                int s0 = g_srca[j], s1 = g_srca[j + 1];
                float al0 = g_alpha[j], al1 = g_alpha[j + 1];
                const float4 h0 = ldh4(&g_h[s0 * C + c]);
                const float4 h1 = ldh4(&g_h[s1 * C + c]);
                acc0.x += al0 * h0.x; acc1.x += al1 * h1.x;
                acc0.y += al0 * h0.y; acc1.y += al1 * h1.y;
                acc0.z += al0 * h0.z; acc1.z += al1 * h1.z;
                acc0.w += al0 * h0.w; acc1.w += al1 * h1.w;
            }
            if (j < end) {
                int s = g_srca[j];
                float al = g_alpha[j];
                const float4 hv = ldh4(&g_h[s * C + c]);
                acc0.x += al * hv.x;
                acc0.y += al * hv.y;
                acc0.z += al * hv.z;
                acc0.w += al * hv.w;
            }
            acc0.x += acc1.x; acc0.y += acc1.y; acc0.z += acc1.z; acc0.w += acc1.w;
        }
        *(float4*)&ts[row * C + c] = acc0;
    }
    __syncthreads();

    // GEMM phase: 8 rows per warp, f32x2 packed FMA
    ull acc2[8][2];
#pragma unroll
    for (int i = 0; i < 8; i++) { acc2[i][0] = 0ull; acc2[i][1] = 0ull; }

    for (int k4 = 0; k4 < C; k4 += 4) {
        ull wa[4], wb[4];
#pragma unroll
        for (int kk = 0; kk < 4; kk++) {
            float4 wv = __ldg((const float4*)&W2[(k4 + kk) * C + c]);
            PK2(wa[kk], wv.x, wv.y);
            PK2(wb[kk], wv.z, wv.w);
        }
#pragma unroll
        for (int i = 0; i < 8; i++) {
            float4 tv = *(const float4*)&ts[(warp * 8 + i) * C + k4];
            ull t0, t1, t2, t3;
            PK2(t0, tv.x, tv.x);
            PK2(t1, tv.y, tv.y);
            PK2(t2, tv.z, tv.z);
            PK2(t3, tv.w, tv.w);
            FMA2(acc2[i][0], t0, wa[0]); FMA2(acc2[i][1], t0, wb[0]);
            FMA2(acc2[i][0], t1, wa[1]); FMA2(acc2[i][1], t1, wb[1]);
            FMA2(acc2[i][0], t2, wa[2]); FMA2(acc2[i][1], t2, wb[2]);
            FMA2(acc2[i][0], t3, wa[3]); FMA2(acc2[i][1], t3, wb[3]);
        }
    }

    float4 bb  = *(const float4*)&bg[c];
    float4 w3a = *(const float4*)&W3[c * 2];
    float4 w3b = *(const float4*)&W3[c * 2 + 4];
    float b30 = b3[0], b31 = b3[1];
#pragma unroll
    for (int i = 0; i < 8; i++) {
        float a0, a1, a2, a3;
        UNPK2(a0, a1, acc2[i][0]);
        UNPK2(a2, a3, acc2[i][1]);
        float vx = fmaxf(a0 + bb.x, 0.f);
        float vy = fmaxf(a1 + bb.y, 0.f);
        float vz = fmaxf(a2 + bb.z, 0.f);
        float vw = fmaxf(a3 + bb.w, 0.f);
        float p0 = vx * w3a.x + vy * w3a.z + vz * w3b.x + vw * w3b.z;
        float p1 = vx * w3a.y + vy * w3a.w + vz * w3b.y + vw * w3b.w;
#pragma unroll
        for (int o = 16; o; o >>= 1) {
            p0 += __shfl_xor_sync(0xffffffffu, p0, o);
            p1 += __shfl_xor_sync(0xffffffffu, p1, o);
        }
        int r = rowBase + warp * 8 + i;
        if (lane == 0 && r < NN) {
            out[r * 2 + 0] = p0 + b30;
            out[r * 2 + 1] = p1 + b31;
        }
    }
}

// ---------------- launch ----------------
extern "C" void kernel_launch(void* const* d_in, const int* in_sizes, int n_in,
                              void* d_out, int out_size) {
    const float* x    = (const float*)d_in[0];
    const int*   ei   = (const int*)  d_in[1];
    const float* ew   = (const float*)d_in[2];
    const float* Wl   = (const float*)d_in[3];
    const float* bl   = (const float*)d_in[4];
    const float* Wr   = (const float*)d_in[5];
    const float* br   = (const float*)d_in[6];
    const float* We   = (const float*)d_in[7];
    const float* att  = (const float*)d_in[8];
    const float* bgat = (const float*)d_in[9];
    const float* W2   = (const float*)d_in[10];
    const float* bgcn = (const float*)d_in[11];
    const float* W3   = (const float*)d_in[12];
    const float* b3   = (const float*)d_in[13];
    float* out = (float*)d_out;

    const int TPB = 256;
    k_zerocnt<<<(NN + TPB - 1) / TPB, TPB>>>();
    k_hist   <<<(ET + TPB - 1) / TPB, TPB>>>(ei, out);
    k_scan   <<<1, 1024>>>();
    k_scatter<<<(ET + TPB - 1) / TPB, TPB>>>(ei, ew);
    k_lin    <<<(NN * 64 + TPB - 1) / TPB, TPB>>>(x, Wl, bl, Wr, br);
    k_gat    <<<(NN * 32 + TPB - 1) / TPB, TPB>>>(We, att, bgat, out);
    k_gemm   <<<(NN + 63) / 64, TPB>>>(W2, bgcn, W3, b3, out);
}

// round 16
// speedup vs baseline: 1.1655x; 1.0603x over previous
#include <cuda_runtime.h>
#include <cuda_fp16.h>

#define NN   100000
#define EE   1600000
#define ET   (EE + NN)     // 1,700,000
#define C    128
#define DIN  6

typedef unsigned long long ull;

// ---------------- device scratch ----------------
__device__ __half g_xl[NN * C];    // fp16 feature table (gathered by k_gat)
__device__ float  g_xr[NN * C];    // fp32 (coalesced per-node read)
__device__ __half g_h [NN * C];    // fp16 feature table (gathered by k_gemm)
__device__ float  g_ex[ET];        // CSR-ordered exp(logit)
__device__ float  g_alpha[ET];     // CSR-ordered alpha
__device__ uint4  g_csr[ET];       // (src, e0bits, e1bits, eid) — single STG.128
__device__ int    g_cnt[NN];
__device__ int    g_rowptr[NN + 1];
__device__ int    g_cur[NN];

// packed f32x2 helpers (Blackwell)
#define PK2(d, lo, hi)    asm("mov.b64 %0, {%1,%2};" : "=l"(d) : "f"(lo), "f"(hi))
#define UNPK2(lo, hi, s)  asm("mov.b64 {%0,%1}, %2;" : "=f"(lo), "=f"(hi) : "l"(s))
#define ADD2(d, a, b)     asm("add.rn.f32x2 %0, %1, %2;" : "=l"(d) : "l"(a), "l"(b))
#define MUL2(d, a, b)     asm("mul.rn.f32x2 %0, %1, %2;" : "=l"(d) : "l"(a), "l"(b))
#define FMA2D(d, a, b, c) asm("fma.rn.f32x2 %0, %1, %2, %3;" : "=l"(d) : "l"(a), "l"(b), "l"(c))
#define FMA2(d, a, b)     asm("fma.rn.f32x2 %0, %1, %2, %0;" : "+l"(d) : "l"(a), "l"(b))
#define AND64(d, a)       asm("and.b64 %0, %1, 0x7FFFFFFF7FFFFFFF;" : "=l"(d) : "l"(a))

// load 4 fp16 channels -> float4 (8 bytes)
__device__ __forceinline__ float4 ldh4(const __half* p) {
    uint2 u = *(const uint2*)p;
    __half2 h0, h1;
    *(unsigned*)&h0 = u.x; *(unsigned*)&h1 = u.y;
    float2 f0 = __half22float2(h0), f1 = __half22float2(h1);
    return make_float4(f0.x, f0.y, f1.x, f1.y);
}

// ---------------- K0 ----------------
__global__ void k_zerocnt() {
    int i = blockIdx.x * blockDim.x + threadIdx.x;
    if (i < NN) g_cnt[i] = 0;
}

// ---------------- K1: histogram + src/dst stack output ----------------
__global__ void k_hist(const int* __restrict__ ei, float* __restrict__ out) {
    int e = blockIdx.x * blockDim.x + threadIdx.x;
    if (e >= ET) return;
    int s, d;
    if (e < EE) { s = ei[e]; d = ei[EE + e]; }
    else        { s = e - EE; d = s; }
    atomicAdd(&g_cnt[d], 1);
    out[NN * 2 + e]      = (float)s;
    out[NN * 2 + ET + e] = (float)d;
}

// ---------------- K2: exclusive scan ----------------
__global__ void k_scan() {
    __shared__ int ssum[1024];
    const int CH = (NN + 1023) / 1024;
    int t = threadIdx.x;
    int beg = t * CH; if (beg > NN) beg = NN;
    int end = beg + CH; if (end > NN) end = NN;
    int s = 0;
    for (int j = beg; j < end; j++) s += g_cnt[j];
    ssum[t] = s;
    __syncthreads();
    for (int off = 1; off < 1024; off <<= 1) {
        int v = (t >= off) ? ssum[t - off] : 0;
        __syncthreads();
        ssum[t] += v;
        __syncthreads();
    }
    int run = t ? ssum[t - 1] : 0;
    for (int j = beg; j < end; j++) {
        g_rowptr[j] = run;
        g_cur[j]    = run;
        run += g_cnt[j];
    }
    if (t == 0) g_rowptr[NN] = ET;
}

// ---------------- K3: scatter edges into CSR slots (single STG.128) ----------------
__global__ void k_scatter(const int* __restrict__ ei, const float* __restrict__ ew) {
    int e = blockIdx.x * blockDim.x + threadIdx.x;
    if (e >= ET) return;
    int s, d; float e0 = 0.f, e1 = 0.f;
    if (e < EE) {
        s = ei[e]; d = ei[EE + e];
        float2 v = *(const float2*)&ew[2 * e];
        e0 = v.x; e1 = v.y;
    } else { s = e - EE; d = s; }
    int pos = atomicAdd(&g_cur[d], 1);
    g_csr[pos] = make_uint4((unsigned)s, __float_as_uint(e0),
                            __float_as_uint(e1), (unsigned)e);
}

// ---------------- K4: xl = fp16(x@Wl + bl) ; xr = x@Wr + br ----------------
__global__ void k_lin(const float* __restrict__ x,
                      const float* __restrict__ Wl, const float* __restrict__ bl,
                      const float* __restrict__ Wr, const float* __restrict__ br) {
    int idx = blockIdx.x * blockDim.x + threadIdx.x;
    if (idx >= NN * 64) return;
    int n = idx >> 6, cp = (idx & 63) * 2;
    float a0 = bl[cp], a1 = bl[cp + 1];
    float b0 = br[cp], b1 = br[cp + 1];
#pragma unroll
    for (int k = 0; k < DIN; k++) {
        float xv = x[n * DIN + k];
        a0 += xv * Wl[k * C + cp];
        a1 += xv * Wl[k * C + cp + 1];
        b0 += xv * Wr[k * C + cp];
        b1 += xv * Wr[k * C + cp + 1];
    }
    ((__half2*)g_xl)[idx] = __floats2half2_rn(a0, a1);
    *(float2*)&g_xr[n * C + cp] = make_float2(b0, b1);
}

// packed logit for one edge's 4 channels on this lane; also emits packed a0,a1 for reuse
__device__ __forceinline__ float lane_logit_pk(uint2 u,
                                               ull xr0, ull xr1,
                                               ull e0p, ull e1p,
                                               ull w00, ull w01, ull w10, ull w11,
                                               ull at0, ull at1,
                                               ull c04, ull c06,
                                               ull& a0, ull& a1) {
    float2 f01 = __half22float2(*(__half2*)&u.x);
    float2 f23 = __half22float2(*(__half2*)&u.y);
    PK2(a0, f01.x, f01.y);
    PK2(a1, f23.x, f23.y);
    ull m, am, t, r, pacc;
    ADD2(m, a0, xr0);
    FMA2D(m, e0p, w00, m);
    FMA2D(m, e1p, w10, m);
    AND64(am, m);
    MUL2(t, am, c04);
    FMA2D(r, m, c06, t);              // leaky_relu(m, 0.2) = 0.6m + 0.4|m|
    MUL2(pacc, r, at0);
    ADD2(m, a1, xr1);
    FMA2D(m, e0p, w01, m);
    FMA2D(m, e1p, w11, m);
    AND64(am, m);
    MUL2(t, am, c04);
    FMA2D(r, m, c06, t);
    FMA2(pacc, r, at1);
    float plo, phi;
    UNPK2(plo, phi, pacc);
    return plo + phi;
}

// ---------------- K5: fused GATv2, single gather pass, packed f32x2 math ----------------
__global__ void __launch_bounds__(256, 4)
k_gat(const float* __restrict__ We, const float* __restrict__ att,
      const float* __restrict__ bgat, float* __restrict__ out) {
    int node = (blockIdx.x * blockDim.x + threadIdx.x) >> 5;
    int lane = threadIdx.x & 31;
    if (node >= NN) return;
    int c = lane * 4;

    ull w00, w01, w10, w11, at0, at1, xr0, xr1, c04, c06;
    {
        float4 A = *(const float4*)&We[c];
        PK2(w00, A.x, A.y); PK2(w01, A.z, A.w);
        A = *(const float4*)&We[C + c];
        PK2(w10, A.x, A.y); PK2(w11, A.z, A.w);
        A = *(const float4*)&att[c];
        PK2(at0, A.x, A.y); PK2(at1, A.z, A.w);
        A = *(const float4*)&g_xr[node * C + c];
        PK2(xr0, A.x, A.y); PK2(xr1, A.z, A.w);
    }
    PK2(c04, 0.4f, 0.4f);
    PK2(c06, 0.6f, 0.6f);

    int beg = g_rowptr[node], end = g_rowptr[node + 1];
    float den = 0.f;
    ull acc0 = 0ull, acc1 = 0ull;     // packed fp32 accumulators (0.0,0.0)

    int j = beg;
    for (; j + 3 < end; j += 4) {
        uint4 r0 = g_csr[j], r1 = g_csr[j + 1], r2 = g_csr[j + 2], r3 = g_csr[j + 3];
        uint2 u0 = *(const uint2*)&g_xl[r0.x * C + c];
        uint2 u1 = *(const uint2*)&g_xl[r1.x * C + c];
        uint2 u2 = *(const uint2*)&g_xl[r2.x * C + c];
        uint2 u3 = *(const uint2*)&g_xl[r3.x * C + c];
        ull e00, e01, e10, e11, e20, e21, e30, e31;
        float f;
        f = __uint_as_float(r0.y); PK2(e00, f, f);
        f = __uint_as_float(r0.z); PK2(e01, f, f);
        f = __uint_as_float(r1.y); PK2(e10, f, f);
        f = __uint_as_float(r1.z); PK2(e11, f, f);
        f = __uint_as_float(r2.y); PK2(e20, f, f);
        f = __uint_as_float(r2.z); PK2(e21, f, f);
        f = __uint_as_float(r3.y); PK2(e30, f, f);
        f = __uint_as_float(r3.z); PK2(e31, f, f);
        ull a00, a01, a10, a11, a20, a21, a30, a31;
        float p0 = lane_logit_pk(u0, xr0, xr1, e00, e01, w00, w01, w10, w11, at0, at1, c04, c06, a00, a01);
        float p1 = lane_logit_pk(u1, xr0, xr1, e10, e11, w00, w01, w10, w11, at0, at1, c04, c06, a10, a11);
        float p2 = lane_logit_pk(u2, xr0, xr1, e20, e21, w00, w01, w10, w11, at0, at1, c04, c06, a20, a21);
        float p3 = lane_logit_pk(u3, xr0, xr1, e30, e31, w00, w01, w10, w11, at0, at1, c04, c06, a30, a31);
#pragma unroll
        for (int o = 16; o; o >>= 1) {
            p0 += __shfl_xor_sync(0xffffffffu, p0, o);
            p1 += __shfl_xor_sync(0xffffffffu, p1, o);
            p2 += __shfl_xor_sync(0xffffffffu, p2, o);
            p3 += __shfl_xor_sync(0xffffffffu, p3, o);
        }
        float v0 = __expf(p0), v1 = __expf(p1), v2 = __expf(p2), v3 = __expf(p3);
        if (lane == 0) {
            g_ex[j] = v0; g_ex[j + 1] = v1; g_ex[j + 2] = v2; g_ex[j + 3] = v3;
        }
        den += (v0 + v1) + (v2 + v3);
        ull vp;
        PK2(vp, v0, v0); FMA2(acc0, vp, a00); FMA2(acc1, vp, a01);
        PK2(vp, v1, v1); FMA2(acc0, vp, a10); FMA2(acc1, vp, a11);
        PK2(vp, v2, v2); FMA2(acc0, vp, a20); FMA2(acc1, vp, a21);
        PK2(vp, v3, v3); FMA2(acc0, vp, a30); FMA2(acc1, vp, a31);
    }
    for (; j < end; j++) {
        uint4 r = g_csr[j];
        uint2 u = *(const uint2*)&g_xl[r.x * C + c];
        ull e0p, e1p, a0, a1;
        float f0 = __uint_as_float(r.y), f1 = __uint_as_float(r.z);
        PK2(e0p, f0, f0); PK2(e1p, f1, f1);
        float p = lane_logit_pk(u, xr0, xr1, e0p, e1p, w00, w01, w10, w11, at0, at1, c04, c06, a0, a1);
#pragma unroll
        for (int o = 16; o; o >>= 1) p += __shfl_xor_sync(0xffffffffu, p, o);
        float v = __expf(p);
        if (lane == 0) g_ex[j] = v;
        den += v;
        ull vp;
        PK2(vp, v, v);
        FMA2(acc0, vp, a0); FMA2(acc1, vp, a1);
    }
    float inv = 1.f / den;

    // pass B: alpha write-out, lanes parallel over edges
    for (int jj = beg + lane; jj < end; jj += 32) {
        float al = g_ex[jj] * inv;
        g_alpha[jj] = al;
        out[(long long)NN * 2 + 2LL * ET + g_csr[jj].w] = al;
    }

    float ax, ay, az, aw;
    UNPK2(ax, ay, acc0);
    UNPK2(az, aw, acc1);
    float4 bb = *(const float4*)&bgat[c];
    float hx = fmaxf(ax * inv + bb.x, 0.f);
    float hy = fmaxf(ay * inv + bb.y, 0.f);
    float hz = fmaxf(az * inv + bb.z, 0.f);
    float hw = fmaxf(aw * inv + bb.w, 0.f);
    uint2 hu;
    *(__half2*)&hu.x = __floats2half2_rn(hx, hy);
    *(__half2*)&hu.y = __floats2half2_rn(hz, hw);
    *(uint2*)&g_h[node * C + c] = hu;
}

// ---------------- K6: fused GCN gather + GEMM + head (NO block barrier — per-warp rows) ----------------
__global__ void k_gemm(const float* __restrict__ W2, const float* __restrict__ bg,
                       const float* __restrict__ W3, const float* __restrict__ b3,
                       float* __restrict__ out) {
    __shared__ float ts[64 * C];
    int lane = threadIdx.x & 31, warp = threadIdx.x >> 5;
    int rowBase = blockIdx.x * 64;
    int c = lane * 4;

    // gather phase: t[node] = sum alpha * h[src]  (deg==1 => norm==alpha)
    // each warp's 8 rows of ts are private to that warp — no block barrier needed.
#pragma unroll
    for (int i = 0; i < 8; i++) {
        int row = warp * 8 + i;
        int node = rowBase + row;
        float4 acc0 = make_float4(0.f, 0.f, 0.f, 0.f);
        float4 acc1 = make_float4(0.f, 0.f, 0.f, 0.f);
        if (node < NN) {
            int beg = g_rowptr[node], end = g_rowptr[node + 1];
            int j = beg;
            for (; j + 1 < end; j += 2) {
                int s0 = g_csr[j].x, s1 = g_csr[j + 1].x;
                float al0 = g_alpha[j], al1 = g_alpha[j + 1];
                const float4 h0 = ldh4(&g_h[s0 * C + c]);
                const float4 h1 = ldh4(&g_h[s1 * C + c]);
                acc0.x += al0 * h0.x; acc1.x += al1 * h1.x;
                acc0.y += al0 * h0.y; acc1.y += al1 * h1.y;
                acc0.z += al0 * h0.z; acc1.z += al1 * h1.z;
                acc0.w += al0 * h0.w; acc1.w += al1 * h1.w;
            }
            if (j < end) {
                int s = g_csr[j].x;
                float al = g_alpha[j];
                const float4 hv = ldh4(&g_h[s * C + c]);
                acc0.x += al * hv.x;
                acc0.y += al * hv.y;
                acc0.z += al * hv.z;
                acc0.w += al * hv.w;
            }
            acc0.x += acc1.x; acc0.y += acc1.y; acc0.z += acc1.z; acc0.w += acc1.w;
        }
        *(float4*)&ts[row * C + c] = acc0;
    }
    __syncwarp();    // warp-local visibility only; warps proceed independently

    // GEMM phase: 8 rows per warp, f32x2 packed FMA
    ull acc2[8][2];
#pragma unroll
    for (int i = 0; i < 8; i++) { acc2[i][0] = 0ull; acc2[i][1] = 0ull; }

    for (int k4 = 0; k4 < C; k4 += 4) {
        ull wa[4], wb[4];
#pragma unroll
        for (int kk = 0; kk < 4; kk++) {
            float4 wv = __ldg((const float4*)&W2[(k4 + kk) * C + c]);
            PK2(wa[kk], wv.x, wv.y);
            PK2(wb[kk], wv.z, wv.w);
        }
#pragma unroll
        for (int i = 0; i < 8; i++) {
            float4 tv = *(const float4*)&ts[(warp * 8 + i) * C + k4];
            ull t0, t1, t2, t3;
            PK2(t0, tv.x, tv.x);
            PK2(t1, tv.y, tv.y);
            PK2(t2, tv.z, tv.z);
            PK2(t3, tv.w, tv.w);
            FMA2(acc2[i][0], t0, wa[0]); FMA2(acc2[i][1], t0, wb[0]);
            FMA2(acc2[i][0], t1, wa[1]); FMA2(acc2[i][1], t1, wb[1]);
            FMA2(acc2[i][0], t2, wa[2]); FMA2(acc2[i][1], t2, wb[2]);
            FMA2(acc2[i][0], t3, wa[3]); FMA2(acc2[i][1], t3, wb[3]);
        }
    }

    float4 bb  = *(const float4*)&bg[c];
    float4 w3a = *(const float4*)&W3[c * 2];
    float4 w3b = *(const float4*)&W3[c * 2 + 4];
    float b30 = b3[0], b31 = b3[1];
#pragma unroll
    for (int i = 0; i < 8; i++) {
        float a0, a1, a2, a3;
        UNPK2(a0, a1, acc2[i][0]);
        UNPK2(a2, a3, acc2[i][1]);
        float vx = fmaxf(a0 + bb.x, 0.f);
        float vy = fmaxf(a1 + bb.y, 0.f);
        float vz = fmaxf(a2 + bb.z, 0.f);
        float vw = fmaxf(a3 + bb.w, 0.f);
        float p0 = vx * w3a.x + vy * w3a.z + vz * w3b.x + vw * w3b.z;
        float p1 = vx * w3a.y + vy * w3a.w + vz * w3b.y + vw * w3b.w;
#pragma unroll
        for (int o = 16; o; o >>= 1) {
            p0 += __shfl_xor_sync(0xffffffffu, p0, o);
            p1 += __shfl_xor_sync(0xffffffffu, p1, o);
        }
        int r = rowBase + warp * 8 + i;
        if (lane == 0 && r < NN) {
            out[r * 2 + 0] = p0 + b30;
            out[r * 2 + 1] = p1 + b31;
        }
    }
}

// ---------------- launch ----------------
extern "C" void kernel_launch(void* const* d_in, const int* in_sizes, int n_in,
                              void* d_out, int out_size) {
    const float* x    = (const float*)d_in[0];
    const int*   ei   = (const int*)  d_in[1];
    const float* ew   = (const float*)d_in[2];
    const float* Wl   = (const float*)d_in[3];
    const float* bl   = (const float*)d_in[4];
    const float* Wr   = (const float*)d_in[5];
    const float* br   = (const float*)d_in[6];
    const float* We   = (const float*)d_in[7];
    const float* att  = (const float*)d_in[8];
    const float* bgat = (const float*)d_in[9];
    const float* W2   = (const float*)d_in[10];
    const float* bgcn = (const float*)d_in[11];
    const float* W3   = (const float*)d_in[12];
    const float* b3   = (const float*)d_in[13];
    float* out = (float*)d_out;

    const int TPB = 256;
    k_zerocnt<<<(NN + TPB - 1) / TPB, TPB>>>();
    k_hist   <<<(ET + TPB - 1) / TPB, TPB>>>(ei, out);
    k_scan   <<<1, 1024>>>();
    k_scatter<<<(ET + TPB - 1) / TPB, TPB>>>(ei, ew);
    k_lin    <<<(NN * 64 + TPB - 1) / TPB, TPB>>>(x, Wl, bl, Wr, br);
    k_gat    <<<(NN * 32 + TPB - 1) / TPB, TPB>>>(We, att, bgat, out);
    k_gemm   <<<(NN + 63) / 64, TPB>>>(W2, bgcn, W3, b3, out);
}